// round 13
// baseline (speedup 1.0000x reference)
#include <cuda_runtime.h>
#include <cstdint>

// ---- static problem config (matches reference) ----
#define BB     2
#define HH     16
#define LL     16384
#define DH     128
#define TPF    512
#define CAP    (LL + TPF)        // 16896
#define BSZ    128
#define NBUCK  32                // L / TPF / PD
#define ROWS   (2 * BB * HH)     // 64
#define ROW_V4 (CAP * DH / 4)    // 540672 float4 per row
#define KVROW_V4 (TPF * DH / 4)  // 16384 float4 per row in kv
#define KVB    (CAP / BSZ)       // 132 kv blocks
#define QB     ((TPF + BSZ - 1) / BSZ)  // 4 q blocks

// 32 tokens per chunk = 1024 float4 = 4 per thread @ 256 threads.
// Ring window (512-token aligned) and tail (16384) are 32-token aligned
// => every chunk has exactly ONE source (block-uniform).
#define TOK_PER_CHUNK 32
#define CHUNK    (TOK_PER_CHUNK * DH / 4)   // 1024 float4
#define NCHUNKS  (ROW_V4 / CHUNK)           // 528 exactly

__device__ __forceinline__ bool truthy32(const unsigned int* p, int i) {
    return p[i] != 0u;
}

// ---- metadata: block mask + orderings + mask_written + written ----
__device__ void do_meta(const int*          __restrict__ t_pos,
                        const unsigned int* __restrict__ written,
                        const int*          __restrict__ frozen_p,
                        float*              __restrict__ out)
{
    __shared__ unsigned char s_any[KVB];
    __shared__ unsigned char s_all[KVB];
    __shared__ short s_ordp[KVB];
    __shared__ short s_ordf[KVB];
    __shared__ int   s_np, s_nf;
    int tid = threadIdx.x;

    int frame_t   = t_pos[0];
    int ring_base = (frame_t % NBUCK) * TPF;
    int frozen    = frozen_p ? frozen_p[0] : 0;
    // write_step == true (PD = 1)

    const size_t base = (size_t)2 * BB * HH * CAP * DH;  // 138412032
    const size_t off_kvnum  = base;
    const size_t off_kvidx  = base + QB;
    const size_t off_fnum   = off_kvidx + (size_t)QB * KVB;
    const size_t off_fidx   = off_fnum + QB;
    const size_t off_mask   = off_fidx + (size_t)QB * KVB;
    const size_t off_wr     = off_mask + CAP;

    for (int p = tid; p < CAP; p += 256) {
        bool w = truthy32(written, p);
        bool in_ring = (p >= ring_base) && (p < ring_base + TPF);
        bool mw = in_ring ? false : w;
        bool wr = w || (!frozen && in_ring);
        out[off_mask + p] = mw ? 1.0f : 0.0f;
        out[off_wr   + p] = wr ? 1.0f : 0.0f;
    }

    for (int b = tid; b < KVB; b += 256) {
        unsigned char any_ = 0, all_ = 1;
        #pragma unroll 4
        for (int j = 0; j < BSZ; j++) {
            int p = b * BSZ + j;
            bool in_ring = (p >= ring_base) && (p < ring_base + TPF);
            unsigned char m = in_ring ? 0 : (truthy32(written, p) ? 1 : 0);
            any_ |= m;
            all_ &= m;
        }
        s_any[b] = any_;
        s_all[b] = all_;
    }
    __syncthreads();

    if (tid == 0) {
        int np = 0, nf = 0;
        for (int b = 0; b < KVB; b++)
            if (s_any[b] && !s_all[b]) s_ordp[np++] = (short)b;
        { int k = np;
          for (int b = 0; b < KVB; b++)
              if (!(s_any[b] && !s_all[b])) s_ordp[k++] = (short)b; }
        for (int b = 0; b < KVB; b++)
            if (s_all[b]) s_ordf[nf++] = (short)b;
        { int k = nf;
          for (int b = 0; b < KVB; b++)
              if (!s_all[b]) s_ordf[k++] = (short)b; }
        s_np = np; s_nf = nf;
    }
    __syncthreads();

    float fnp = (float)s_np, fnf = (float)s_nf;
    if (tid < QB) {
        out[off_kvnum + tid] = fnp;
        out[off_fnum  + tid] = fnf;
    }
    for (int e = tid; e < QB * KVB; e += 256) {
        int b = e % KVB;
        out[off_kvidx + e] = (float)s_ordp[b];
        out[off_fidx  + e] = (float)s_ordf[b];
    }
}

// ---- fused kernel: grid (NCHUNKS+1, ROWS); extra x-column block 0 does meta ----
__global__ void __launch_bounds__(256)
fused_kernel(const float4*       __restrict__ kv,
             const float4*       __restrict__ buf,
             const int*          __restrict__ t_pos,
             const unsigned int* __restrict__ written,
             const int*          __restrict__ frozen_p,
             float4*             __restrict__ out)
{
    if (blockIdx.x == NCHUNKS) {
        if (blockIdx.y == 0)
            do_meta(t_pos, written, frozen_p, (float*)out);
        return;
    }

    int row = blockIdx.y;
    int t0  = blockIdx.x * TOK_PER_CHUNK;          // first token of this chunk
    int i0  = blockIdx.x * CHUNK + threadIdx.x;    // first float4 idx (thread)

    int frame_t   = __ldg(t_pos);
    int ring_base = (frame_t % NBUCK) * TPF;
    int frozen    = frozen_p ? __ldg(frozen_p) : 0;

    const size_t rowo = (size_t)row * ROW_V4;

    // Resolve the single source for this whole chunk (block-uniform).
    const float4* __restrict__ src;
    if (t0 >= LL) {
        src = kv + (size_t)row * KVROW_V4 + (i0 - LL * (DH / 4));
    } else if (!frozen && t0 >= ring_base && t0 < ring_base + TPF) {
        src = kv + (size_t)row * KVROW_V4 + (i0 - ring_base * (DH / 4));
    } else {
        src = buf + rowo + i0;
    }
    float4* __restrict__ dst = out + rowo + i0;

    // INTERLEAVED load->store pairs, ordering enforced with compiler
    // barriers. Front-batched LDGs (MLP_p1=4) measurably inflate the
    // back-to-back replay time by ~20us via cross-CTA L1tex-queue
    // contention (R7/R8/R10/R11 vs R3/R12 evidence) even though they look
    // faster in an isolated ncu launch.
    #pragma unroll
    for (int u = 0; u < 4; u++) {
        float4 v = __ldcs(src + u * 256);
        __stcs(dst + u * 256, v);
        asm volatile("" ::: "memory");
    }
}

extern "C" void kernel_launch(void* const* d_in, const int* in_sizes, int n_in,
                              void* d_out, int out_size)
{
    const float4*       kv     = (const float4*)d_in[0];
    const float4*       buf    = (const float4*)d_in[1];
    const int*          t_pos  = (const int*)d_in[2];
    const unsigned int* wrt    = (const unsigned int*)d_in[3];
    const int*          frozen = (n_in > 4) ? (const int*)d_in[4] : nullptr;

    (void)in_sizes; (void)out_size;

    dim3 grid(NCHUNKS + 1, ROWS);   // (529, 64)
    fused_kernel<<<grid, 256>>>(kv, buf, t_pos, wrt, frozen, (float4*)d_out);
}

// round 14
// speedup vs baseline: 1.0008x; 1.0008x over previous
#include <cuda_runtime.h>
#include <cstdint>

// ---- static problem config (matches reference) ----
#define BB     2
#define HH     16
#define LL     16384
#define DH     128
#define TPF    512
#define CAP    (LL + TPF)        // 16896
#define BSZ    128
#define NBUCK  32                // L / TPF / PD
#define ROWS   (2 * BB * HH)     // 64
#define ROW_V4 (CAP * DH / 4)    // 540672 float4 per row
#define KVROW_V4 (TPF * DH / 4)  // 16384 float4 per row in kv
#define KVB    (CAP / BSZ)       // 132 kv blocks
#define QB     ((TPF + BSZ - 1) / BSZ)  // 4 q blocks

// 32 tokens per chunk = 1024 float4 = 4 per thread @ 256 threads.
// Ring window (512-token aligned) and tail (16384) are 32-token aligned
// => every chunk has exactly ONE source (block-uniform).
#define TOK_PER_CHUNK 32
#define CHUNK    (TOK_PER_CHUNK * DH / 4)   // 1024 float4
#define NCHUNKS  (ROW_V4 / CHUNK)           // 528 exactly

__device__ __forceinline__ bool truthy32(const unsigned int* p, int i) {
    return p[i] != 0u;
}

// ---- metadata: block mask + orderings + mask_written + written ----
__device__ void do_meta(const int*          __restrict__ t_pos,
                        const unsigned int* __restrict__ written,
                        const int*          __restrict__ frozen_p,
                        float*              __restrict__ out)
{
    __shared__ unsigned char s_any[KVB];
    __shared__ unsigned char s_all[KVB];
    __shared__ short s_ordp[KVB];
    __shared__ short s_ordf[KVB];
    __shared__ int   s_np, s_nf;
    int tid = threadIdx.x;

    int frame_t   = t_pos[0];
    int ring_base = (frame_t % NBUCK) * TPF;
    int frozen    = frozen_p ? frozen_p[0] : 0;
    // write_step == true (PD = 1)

    const size_t base = (size_t)2 * BB * HH * CAP * DH;  // 138412032
    const size_t off_kvnum  = base;
    const size_t off_kvidx  = base + QB;
    const size_t off_fnum   = off_kvidx + (size_t)QB * KVB;
    const size_t off_fidx   = off_fnum + QB;
    const size_t off_mask   = off_fidx + (size_t)QB * KVB;
    const size_t off_wr     = off_mask + CAP;

    for (int p = tid; p < CAP; p += 256) {
        bool w = truthy32(written, p);
        bool in_ring = (p >= ring_base) && (p < ring_base + TPF);
        bool mw = in_ring ? false : w;
        bool wr = w || (!frozen && in_ring);
        out[off_mask + p] = mw ? 1.0f : 0.0f;
        out[off_wr   + p] = wr ? 1.0f : 0.0f;
    }

    for (int b = tid; b < KVB; b += 256) {
        unsigned char any_ = 0, all_ = 1;
        #pragma unroll 4
        for (int j = 0; j < BSZ; j++) {
            int p = b * BSZ + j;
            bool in_ring = (p >= ring_base) && (p < ring_base + TPF);
            unsigned char m = in_ring ? 0 : (truthy32(written, p) ? 1 : 0);
            any_ |= m;
            all_ &= m;
        }
        s_any[b] = any_;
        s_all[b] = all_;
    }
    __syncthreads();

    if (tid == 0) {
        int np = 0, nf = 0;
        for (int b = 0; b < KVB; b++)
            if (s_any[b] && !s_all[b]) s_ordp[np++] = (short)b;
        { int k = np;
          for (int b = 0; b < KVB; b++)
              if (!(s_any[b] && !s_all[b])) s_ordp[k++] = (short)b; }
        for (int b = 0; b < KVB; b++)
            if (s_all[b]) s_ordf[nf++] = (short)b;
        { int k = nf;
          for (int b = 0; b < KVB; b++)
              if (!s_all[b]) s_ordf[k++] = (short)b; }
        s_np = np; s_nf = nf;
    }
    __syncthreads();

    float fnp = (float)s_np, fnf = (float)s_nf;
    if (tid < QB) {
        out[off_kvnum + tid] = fnp;
        out[off_fnum  + tid] = fnf;
    }
    for (int e = tid; e < QB * KVB; e += 256) {
        int b = e % KVB;
        out[off_kvidx + e] = (float)s_ordp[b];
        out[off_fidx  + e] = (float)s_ordf[b];
    }
}

// ---- fused kernel: grid (NCHUNKS+1, ROWS); extra x-column block 0 does meta ----
__global__ void __launch_bounds__(256)
fused_kernel(const float4*       __restrict__ kv,
             const float4*       __restrict__ buf,
             const int*          __restrict__ t_pos,
             const unsigned int* __restrict__ written,
             const int*          __restrict__ frozen_p,
             float4*             __restrict__ out)
{
    if (blockIdx.x == NCHUNKS) {
        if (blockIdx.y == 0)
            do_meta(t_pos, written, frozen_p, (float*)out);
        return;
    }

    int row = blockIdx.y;
    int t0  = blockIdx.x * TOK_PER_CHUNK;          // first token of this chunk
    int i0  = blockIdx.x * CHUNK + threadIdx.x;    // first float4 idx (thread)

    int frame_t   = __ldg(t_pos);
    int ring_base = (frame_t % NBUCK) * TPF;
    int frozen    = frozen_p ? __ldg(frozen_p) : 0;

    const size_t rowo = (size_t)row * ROW_V4;

    // Resolve the single source for this whole chunk (block-uniform).
    const float4* __restrict__ src;
    if (t0 >= LL) {
        src = kv + (size_t)row * KVROW_V4 + (i0 - LL * (DH / 4));
    } else if (!frozen && t0 >= ring_base && t0 < ring_base + TPF) {
        src = kv + (size_t)row * KVROW_V4 + (i0 - ring_base * (DH / 4));
    } else {
        src = buf + rowo + i0;
    }
    float4* __restrict__ dst = out + rowo + i0;

    // PAIRWISE interleave: MLP_p1 = 2. Measured spectrum on this bench:
    // MLP_p1=1 -> ~160us total, MLP_p1=4 -> ~172-177us (cross-CTA L1tex
    // queue contention at replay boundaries). oe*MLP_p1 = 16 ~= Q_th, the
    // untested midpoint.
    #pragma unroll
    for (int u = 0; u < 2; u++) {
        float4 a = __ldcs(src + (2 * u) * 256);
        float4 b = __ldcs(src + (2 * u + 1) * 256);
        __stcs(dst + (2 * u) * 256, a);
        __stcs(dst + (2 * u + 1) * 256, b);
        asm volatile("" ::: "memory");
    }
}

extern "C" void kernel_launch(void* const* d_in, const int* in_sizes, int n_in,
                              void* d_out, int out_size)
{
    const float4*       kv     = (const float4*)d_in[0];
    const float4*       buf    = (const float4*)d_in[1];
    const int*          t_pos  = (const int*)d_in[2];
    const unsigned int* wrt    = (const unsigned int*)d_in[3];
    const int*          frozen = (n_in > 4) ? (const int*)d_in[4] : nullptr;

    (void)in_sizes; (void)out_size;

    dim3 grid(NCHUNKS + 1, ROWS);   // (529, 64)
    fused_kernel<<<grid, 256>>>(kv, buf, t_pos, wrt, frozen, (float4*)d_out);
}

// round 15
// speedup vs baseline: 1.0050x; 1.0042x over previous
#include <cuda_runtime.h>
#include <cstdint>

// ---- static problem config (matches reference) ----
#define BB     2
#define HH     16
#define LL     16384
#define DH     128
#define TPF    512
#define CAP    (LL + TPF)        // 16896
#define BSZ    128
#define NBUCK  32                // L / TPF / PD
#define ROWS   (2 * BB * HH)     // 64
#define ROW_V4 (CAP * DH / 4)    // 540672 float4 per row
#define KVROW_V4 (TPF * DH / 4)  // 16384 float4 per row in kv
#define KVB    (CAP / BSZ)       // 132 kv blocks
#define QB     ((TPF + BSZ - 1) / BSZ)  // 4 q blocks

#define NTHREADS 512
// 64 tokens per chunk = 2048 float4 = 4 per thread @ 512 threads.
// Ring window (512-token aligned) and tail (16384) are 64-token aligned
// => every chunk has exactly ONE source (block-uniform).
#define TOK_PER_CHUNK 64
#define CHUNK    (TOK_PER_CHUNK * DH / 4)   // 2048 float4
#define NCHUNKS  (ROW_V4 / CHUNK)           // 264 exactly

__device__ __forceinline__ bool truthy32(const unsigned int* p, int i) {
    return p[i] != 0u;
}

// ---- metadata: block mask + orderings + mask_written + written ----
__device__ void do_meta(const int*          __restrict__ t_pos,
                        const unsigned int* __restrict__ written,
                        const int*          __restrict__ frozen_p,
                        float*              __restrict__ out)
{
    __shared__ unsigned char s_any[KVB];
    __shared__ unsigned char s_all[KVB];
    __shared__ short s_ordp[KVB];
    __shared__ short s_ordf[KVB];
    __shared__ int   s_np, s_nf;
    int tid = threadIdx.x;

    int frame_t   = t_pos[0];
    int ring_base = (frame_t % NBUCK) * TPF;
    int frozen    = frozen_p ? frozen_p[0] : 0;
    // write_step == true (PD = 1)

    const size_t base = (size_t)2 * BB * HH * CAP * DH;  // 138412032
    const size_t off_kvnum  = base;
    const size_t off_kvidx  = base + QB;
    const size_t off_fnum   = off_kvidx + (size_t)QB * KVB;
    const size_t off_fidx   = off_fnum + QB;
    const size_t off_mask   = off_fidx + (size_t)QB * KVB;
    const size_t off_wr     = off_mask + CAP;

    for (int p = tid; p < CAP; p += NTHREADS) {
        bool w = truthy32(written, p);
        bool in_ring = (p >= ring_base) && (p < ring_base + TPF);
        bool mw = in_ring ? false : w;
        bool wr = w || (!frozen && in_ring);
        out[off_mask + p] = mw ? 1.0f : 0.0f;
        out[off_wr   + p] = wr ? 1.0f : 0.0f;
    }

    for (int b = tid; b < KVB; b += NTHREADS) {
        unsigned char any_ = 0, all_ = 1;
        #pragma unroll 4
        for (int j = 0; j < BSZ; j++) {
            int p = b * BSZ + j;
            bool in_ring = (p >= ring_base) && (p < ring_base + TPF);
            unsigned char m = in_ring ? 0 : (truthy32(written, p) ? 1 : 0);
            any_ |= m;
            all_ &= m;
        }
        s_any[b] = any_;
        s_all[b] = all_;
    }
    __syncthreads();

    if (tid == 0) {
        int np = 0, nf = 0;
        for (int b = 0; b < KVB; b++)
            if (s_any[b] && !s_all[b]) s_ordp[np++] = (short)b;
        { int k = np;
          for (int b = 0; b < KVB; b++)
              if (!(s_any[b] && !s_all[b])) s_ordp[k++] = (short)b; }
        for (int b = 0; b < KVB; b++)
            if (s_all[b]) s_ordf[nf++] = (short)b;
        { int k = nf;
          for (int b = 0; b < KVB; b++)
              if (!s_all[b]) s_ordf[k++] = (short)b; }
        s_np = np; s_nf = nf;
    }
    __syncthreads();

    float fnp = (float)s_np, fnf = (float)s_nf;
    if (tid < QB) {
        out[off_kvnum + tid] = fnp;
        out[off_fnum  + tid] = fnf;
    }
    for (int e = tid; e < QB * KVB; e += NTHREADS) {
        int b = e % KVB;
        out[off_kvidx + e] = (float)s_ordp[b];
        out[off_fidx  + e] = (float)s_ordf[b];
    }
}

// ---- fused kernel: grid (NCHUNKS+1, ROWS); extra x-column block 0 does meta ----
__global__ void __launch_bounds__(NTHREADS)
fused_kernel(const float4*       __restrict__ kv,
             const float4*       __restrict__ buf,
             const int*          __restrict__ t_pos,
             const unsigned int* __restrict__ written,
             const int*          __restrict__ frozen_p,
             float4*             __restrict__ out)
{
    if (blockIdx.x == NCHUNKS) {
        if (blockIdx.y == 0)
            do_meta(t_pos, written, frozen_p, (float*)out);
        return;
    }

    int row = blockIdx.y;
    int t0  = blockIdx.x * TOK_PER_CHUNK;          // first token of this chunk
    int i0  = blockIdx.x * CHUNK + threadIdx.x;    // first float4 idx (thread)

    int frame_t   = __ldg(t_pos);
    int ring_base = (frame_t % NBUCK) * TPF;
    int frozen    = frozen_p ? __ldg(frozen_p) : 0;

    const size_t rowo = (size_t)row * ROW_V4;

    // Resolve the single source for this whole chunk (block-uniform).
    const float4* __restrict__ src;
    if (t0 >= LL) {
        src = kv + (size_t)row * KVROW_V4 + (i0 - LL * (DH / 4));
    } else if (!frozen && t0 >= ring_base && t0 < ring_base + TPF) {
        src = kv + (size_t)row * KVROW_V4 + (i0 - ring_base * (DH / 4));
    } else {
        src = buf + rowo + i0;
    }
    float4* __restrict__ dst = out + rowo + i0;

    // PAIRWISE interleave (MLP_p1 = 2): measured bench plateau ~160us for
    // MLP_p1<=2; MLP_p1=4 regresses to 172-177us via cross-CTA L1tex-queue
    // contention at replay boundaries (invisible to isolated ncu).
    #pragma unroll
    for (int u = 0; u < 2; u++) {
        float4 a = __ldcs(src + (2 * u) * NTHREADS);
        float4 b = __ldcs(src + (2 * u + 1) * NTHREADS);
        __stcs(dst + (2 * u) * NTHREADS, a);
        __stcs(dst + (2 * u + 1) * NTHREADS, b);
        asm volatile("" ::: "memory");
    }
}

extern "C" void kernel_launch(void* const* d_in, const int* in_sizes, int n_in,
                              void* d_out, int out_size)
{
    const float4*       kv     = (const float4*)d_in[0];
    const float4*       buf    = (const float4*)d_in[1];
    const int*          t_pos  = (const int*)d_in[2];
    const unsigned int* wrt    = (const unsigned int*)d_in[3];
    const int*          frozen = (n_in > 4) ? (const int*)d_in[4] : nullptr;

    (void)in_sizes; (void)out_size;

    dim3 grid(NCHUNKS + 1, ROWS);   // (265, 64)
    fused_kernel<<<grid, NTHREADS>>>(kv, buf, t_pos, wrt, frozen, (float4*)d_out);
}

// round 16
// speedup vs baseline: 1.0052x; 1.0002x over previous
#include <cuda_runtime.h>
#include <cstdint>

// ---- static problem config (matches reference) ----
#define BB     2
#define HH     16
#define LL     16384
#define DH     128
#define TPF    512
#define CAP    (LL + TPF)        // 16896
#define BSZ    128
#define NBUCK  32                // L / TPF / PD
#define ROWS   (2 * BB * HH)     // 64
#define ROW_V4 (CAP * DH / 4)    // 540672 float4 per row
#define KVROW_V4 (TPF * DH / 4)  // 16384 float4 per row in kv
#define KVB    (CAP / BSZ)       // 132 kv blocks
#define QB     ((TPF + BSZ - 1) / BSZ)  // 4 q blocks

#define NTHREADS 512
// 64 tokens per chunk = 2048 float4 = 4 per thread @ 512 threads.
// Ring window (512-token aligned) and tail (16384) are 64-token aligned
// => every chunk has exactly ONE source (block-uniform).
#define TOK_PER_CHUNK 64
#define CHUNK    (TOK_PER_CHUNK * DH / 4)   // 2048 float4
#define NCHUNKS  (ROW_V4 / CHUNK)           // 264 exactly

__device__ __forceinline__ bool truthy32(const unsigned int* p, int i) {
    return p[i] != 0u;
}

// ---- metadata: block mask + orderings + mask_written + written ----
__device__ void do_meta(const int*          __restrict__ t_pos,
                        const unsigned int* __restrict__ written,
                        const int*          __restrict__ frozen_p,
                        float*              __restrict__ out)
{
    __shared__ unsigned char s_any[KVB];
    __shared__ unsigned char s_all[KVB];
    __shared__ short s_ordp[KVB];
    __shared__ short s_ordf[KVB];
    __shared__ int   s_np, s_nf;
    int tid = threadIdx.x;

    int frame_t   = t_pos[0];
    int ring_base = (frame_t % NBUCK) * TPF;
    int frozen    = frozen_p ? frozen_p[0] : 0;
    // write_step == true (PD = 1)

    const size_t base = (size_t)2 * BB * HH * CAP * DH;  // 138412032
    const size_t off_kvnum  = base;
    const size_t off_kvidx  = base + QB;
    const size_t off_fnum   = off_kvidx + (size_t)QB * KVB;
    const size_t off_fidx   = off_fnum + QB;
    const size_t off_mask   = off_fidx + (size_t)QB * KVB;
    const size_t off_wr     = off_mask + CAP;

    for (int p = tid; p < CAP; p += NTHREADS) {
        bool w = truthy32(written, p);
        bool in_ring = (p >= ring_base) && (p < ring_base + TPF);
        bool mw = in_ring ? false : w;
        bool wr = w || (!frozen && in_ring);
        out[off_mask + p] = mw ? 1.0f : 0.0f;
        out[off_wr   + p] = wr ? 1.0f : 0.0f;
    }

    for (int b = tid; b < KVB; b += NTHREADS) {
        unsigned char any_ = 0, all_ = 1;
        #pragma unroll 4
        for (int j = 0; j < BSZ; j++) {
            int p = b * BSZ + j;
            bool in_ring = (p >= ring_base) && (p < ring_base + TPF);
            unsigned char m = in_ring ? 0 : (truthy32(written, p) ? 1 : 0);
            any_ |= m;
            all_ &= m;
        }
        s_any[b] = any_;
        s_all[b] = all_;
    }
    __syncthreads();

    if (tid == 0) {
        int np = 0, nf = 0;
        for (int b = 0; b < KVB; b++)
            if (s_any[b] && !s_all[b]) s_ordp[np++] = (short)b;
        { int k = np;
          for (int b = 0; b < KVB; b++)
              if (!(s_any[b] && !s_all[b])) s_ordp[k++] = (short)b; }
        for (int b = 0; b < KVB; b++)
            if (s_all[b]) s_ordf[nf++] = (short)b;
        { int k = nf;
          for (int b = 0; b < KVB; b++)
              if (!s_all[b]) s_ordf[k++] = (short)b; }
        s_np = np; s_nf = nf;
    }
    __syncthreads();

    float fnp = (float)s_np, fnf = (float)s_nf;
    if (tid < QB) {
        out[off_kvnum + tid] = fnp;
        out[off_fnum  + tid] = fnf;
    }
    for (int e = tid; e < QB * KVB; e += NTHREADS) {
        int b = e % KVB;
        out[off_kvidx + e] = (float)s_ordp[b];
        out[off_fidx  + e] = (float)s_ordf[b];
    }
}

// ---- fused kernel: grid (NCHUNKS+1, ROWS); extra x-column block 0 does meta ----
__global__ void __launch_bounds__(NTHREADS)
fused_kernel(const float4*       __restrict__ kv,
             const float4*       __restrict__ buf,
             const int*          __restrict__ t_pos,
             const unsigned int* __restrict__ written,
             const int*          __restrict__ frozen_p,
             float4*             __restrict__ out)
{
    if (blockIdx.x == NCHUNKS) {
        if (blockIdx.y == 0)
            do_meta(t_pos, written, frozen_p, (float*)out);
        return;
    }

    int row = blockIdx.y;
    int t0  = blockIdx.x * TOK_PER_CHUNK;          // first token of this chunk
    int i0  = blockIdx.x * CHUNK + threadIdx.x;    // first float4 idx (thread)

    int frame_t   = __ldg(t_pos);
    int ring_base = (frame_t % NBUCK) * TPF;
    int frozen    = frozen_p ? __ldg(frozen_p) : 0;

    const size_t rowo = (size_t)row * ROW_V4;

    // Resolve the single source for this whole chunk (block-uniform).
    // kv (16MB total) is read TWICE per replay (tail + ring) and re-read
    // every replay -> keep it L2-resident with CACHED loads. buf (520MB,
    // zero reuse) streams with evict-first loads.
    const float4* __restrict__ src;
    bool from_kv;
    if (t0 >= LL) {
        src = kv + (size_t)row * KVROW_V4 + (i0 - LL * (DH / 4));
        from_kv = true;
    } else if (!frozen && t0 >= ring_base && t0 < ring_base + TPF) {
        src = kv + (size_t)row * KVROW_V4 + (i0 - ring_base * (DH / 4));
        from_kv = true;
    } else {
        src = buf + rowo + i0;
        from_kv = false;
    }
    float4* __restrict__ dst = out + rowo + i0;

    // PAIRWISE interleave (MLP_p1 = 2): measured bench plateau ~160us for
    // MLP_p1<=2; MLP_p1=4 regresses to 172-177us via cross-CTA L1tex-queue
    // contention at replay boundaries (invisible to isolated ncu).
    if (from_kv) {
        #pragma unroll
        for (int u = 0; u < 2; u++) {
            float4 a = src[(2 * u) * NTHREADS];
            float4 b = src[(2 * u + 1) * NTHREADS];
            __stcs(dst + (2 * u) * NTHREADS, a);
            __stcs(dst + (2 * u + 1) * NTHREADS, b);
            asm volatile("" ::: "memory");
        }
    } else {
        #pragma unroll
        for (int u = 0; u < 2; u++) {
            float4 a = __ldcs(src + (2 * u) * NTHREADS);
            float4 b = __ldcs(src + (2 * u + 1) * NTHREADS);
            __stcs(dst + (2 * u) * NTHREADS, a);
            __stcs(dst + (2 * u + 1) * NTHREADS, b);
            asm volatile("" ::: "memory");
        }
    }
}

extern "C" void kernel_launch(void* const* d_in, const int* in_sizes, int n_in,
                              void* d_out, int out_size)
{
    const float4*       kv     = (const float4*)d_in[0];
    const float4*       buf    = (const float4*)d_in[1];
    const int*          t_pos  = (const int*)d_in[2];
    const unsigned int* wrt    = (const unsigned int*)d_in[3];
    const int*          frozen = (n_in > 4) ? (const int*)d_in[4] : nullptr;

    (void)in_sizes; (void)out_size;

    dim3 grid(NCHUNKS + 1, ROWS);   // (265, 64)
    fused_kernel<<<grid, NTHREADS>>>(kv, buf, t_pos, wrt, frozen, (float4*)d_out);
}